// round 8
// baseline (speedup 1.0000x reference)
#include <cuda_runtime.h>

#define B_      512
#define T_      4096
#define THREADS 128
#define ITEMS   2
#define TILE    (THREADS * ITEMS)   // 256 -> grid.x = 16 exact
// row offset in u64: 10r + 2*(r/2). All rows 16B-aligned; lane stride (r0=2*tid)
// = 22 u64 = 44 words == 12 (mod 32) -> LDS.128 8-lane phases conflict-free.
#define ROWOFF(r) ((r) * 10 + ((((r) >> 1)) << 1))

typedef unsigned long long u64;

// ---- packed f32x2 helpers (PTX-only path on sm_103a; ptxas won't auto-fuse) ----
__device__ __forceinline__ u64 pk(float lo, float hi) {
    u64 r; asm("mov.b64 %0,{%1,%2};" : "=l"(r) : "f"(lo), "f"(hi)); return r;
}
__device__ __forceinline__ void upk(u64 v, float& lo, float& hi) {
    asm("mov.b64 {%0,%1},%2;" : "=f"(lo), "=f"(hi) : "l"(v));
}
__device__ __forceinline__ u64 ffma2(u64 a, u64 b, u64 c) {
    u64 d; asm("fma.rn.f32x2 %0,%1,%2,%3;" : "=l"(d) : "l"(a), "l"(b), "l"(c)); return d;
}
__device__ __forceinline__ u64 fmul2(u64 a, u64 b) {
    u64 d; asm("mul.rn.f32x2 %0,%1,%2;" : "=l"(d) : "l"(a), "l"(b)); return d;
}
__device__ __forceinline__ u64 fadd2(u64 a, u64 b) {
    u64 d; asm("add.rn.f32x2 %0,%1,%2;" : "=l"(d) : "l"(a), "l"(b)); return d;
}

// ---- weights, pre-packed for f32x2 ----
// conv weights + small params -> __constant__ (LDC port)
// w1/w2 -> staged via dStage (global) into smem per block (LDS broadcast port)
struct __align__(16) Wts {
    u64 cw[384];   // conv weights (w,w) pairs, [oc][k][ic]
    u64 w1[256];   // w1 as hidden-output pairs: w1[f][j] = (w1[f,2j], w1[f,2j+1])
    u64 w2[16];    // w2 row pairs (w2[h][0], w2[h][1])
    u64 cb[16];    // conv bias (b,b)
    u64 b1[8];     // b1 output pairs
    u64 b2[2];     // (b2[0], b2[1]) + pad
    u64 g[8];      // ln gamma packed (c, c+8)
    u64 bb[8];     // ln beta  packed (c, c+8)
};
__constant__ Wts cW;
__device__   Wts dStage;

__global__ void prep_kernel(const float* __restrict__ conv_w, const float* __restrict__ conv_b,
                            const float* __restrict__ w1,     const float* __restrict__ b1,
                            const float* __restrict__ w2,     const float* __restrict__ b2,
                            const float* __restrict__ ln_g,   const float* __restrict__ ln_b)
{
    const int tid = threadIdx.x;
    for (int j = tid; j < 384; j += 128) {
        const int oc = j / 24, r = j % 24, ic = r / 3, k = r % 3;   // conv_w is (oc, ic, k)
        const float w = conv_w[j];
        dStage.cw[oc * 24 + k * 8 + ic] = pk(w, w);
    }
    for (int j = tid; j < 256; j += 128) {
        const int f = j / 8, q = j % 8;
        dStage.w1[j] = pk(w1[f * 16 + 2 * q], w1[f * 16 + 2 * q + 1]);
    }
    if (tid < 16) dStage.w2[tid] = pk(w2[2 * tid], w2[2 * tid + 1]);
    if (tid < 16) dStage.cb[tid] = pk(conv_b[tid], conv_b[tid]);
    if (tid < 8)  dStage.b1[tid] = pk(b1[2 * tid], b1[2 * tid + 1]);
    if (tid == 0) { dStage.b2[0] = pk(b2[0], b2[1]); dStage.b2[1] = 0ull; }
    if (tid < 8)  dStage.g[tid]  = pk(ln_g[tid], ln_g[tid + 8]);
    if (tid < 8)  dStage.bb[tid] = pk(ln_b[tid], ln_b[tid + 8]);
}

__global__ __launch_bounds__(THREADS, 4)
void bimanual_kernel(const float* __restrict__ x, float* __restrict__ out)
{
    __shared__ __align__(16) u64 xs[ROWOFF(TILE + 2)];   // 16B-aligned staggered x tile
    __shared__ __align__(16) u64 w1s[256];               // w1 pairs (LDS broadcast)
    __shared__ __align__(16) u64 w2s[16];                // w2 row pairs

    const int tid   = threadIdx.x;
    const int b     = blockIdx.y;
    const int tbase = blockIdx.x * TILE;

    // ---- stage x tile (TILE + 2 halo rows; t<0 rows are the conv zero-padding) ----
    for (int tt = tid; tt < TILE + 2; tt += THREADS) {
        const int t = tbase - 2 + tt;
        ulonglong2* row = (ulonglong2*)&xs[ROWOFF(tt)];
        if (t >= 0) {
            const float4* p = (const float4*)(x + ((size_t)b * T_ + t) * 16);
            float4 a = p[0], bq = p[1], c = p[2], d = p[3];
            row[0] = make_ulonglong2(pk(a.x,  c.x), pk(a.y,  c.y));
            row[1] = make_ulonglong2(pk(a.z,  c.z), pk(a.w,  c.w));
            row[2] = make_ulonglong2(pk(bq.x, d.x), pk(bq.y, d.y));
            row[3] = make_ulonglong2(pk(bq.z, d.z), pk(bq.w, d.w));
        } else {
            row[0] = make_ulonglong2(0ull, 0ull);
            row[1] = make_ulonglong2(0ull, 0ull);
            row[2] = make_ulonglong2(0ull, 0ull);
            row[3] = make_ulonglong2(0ull, 0ull);
        }
    }
    // ---- stage w1/w2 pairs into smem (coalesced LDG from global staging) ----
    for (int j = tid; j < 256; j += THREADS) w1s[j] = dStage.w1[j];
    if (tid < 16) w2s[tid] = dStage.w2[tid];
    __syncthreads();

    // ---- per-thread: ITEMS consecutive elements, window rows r0 .. r0+ITEMS+1 ----
    const int r0 = tid * ITEMS;

    // hidden accumulators: 8 packed output-pairs per element
    u64 hid[ITEMS][8];
    #pragma unroll
    for (int j = 0; j < 8; ++j) {
        const u64 bj = cW.b1[j];
        #pragma unroll
        for (int i = 0; i < ITEMS; ++i) hid[i][j] = bj;
    }

    // Scope the x window so it is dead after the conv loop (register pressure).
    {
        u64 xp[ITEMS + 2][8];
        #pragma unroll
        for (int r = 0; r < ITEMS + 2; ++r) {
            const ulonglong2* row = (const ulonglong2*)&xs[ROWOFF(r0 + r)];
            #pragma unroll
            for (int q = 0; q < 4; ++q) {           // 4x LDS.128 per row, conflict-free
                const ulonglong2 v = row[q];
                xp[r][2 * q] = v.x; xp[r][2 * q + 1] = v.y;
            }
        }

        // ---- fused conv(+ReLU) -> rank-1 MLP update ----
        // conv weights via constant port (LDC), w1 via shared port (LDS broadcast)
        #pragma unroll
        for (int oc = 0; oc < 16; ++oc) {
            u64 acc[ITEMS];
            {
                const u64 cb = cW.cb[oc];
                #pragma unroll
                for (int i = 0; i < ITEMS; ++i) acc[i] = cb;
            }
            #pragma unroll
            for (int k = 0; k < 3; ++k) {
                const ulonglong2* wp = (const ulonglong2*)&cW.cw[oc * 24 + k * 8];
                #pragma unroll
                for (int q = 0; q < 4; ++q) {
                    const ulonglong2 wv = wp[q];      // LDC.128 = 2 packed weight pairs
                    #pragma unroll
                    for (int i = 0; i < ITEMS; ++i)
                        acc[i] = ffma2(xp[i + k][2 * q], wv.x, acc[i]);
                    #pragma unroll
                    for (int i = 0; i < ITEMS; ++i)
                        acc[i] = ffma2(xp[i + k][2 * q + 1], wv.y, acc[i]);
                }
            }
            // ReLU + broadcast-splat per element
            u64 vl[ITEMS], vr[ITEMS];
            #pragma unroll
            for (int i = 0; i < ITEMS; ++i) {
                float hl, hr; upk(acc[i], hl, hr);
                hl = fmaxf(hl, 0.f); hr = fmaxf(hr, 0.f);
                vl[i] = pk(hl, hl); vr[i] = pk(hr, hr);
            }
            // rank-1 update of hidden accs: hid += hl*w1[oc,:] + hr*w1[16+oc,:]
            const ulonglong2* wlr = (const ulonglong2*)&w1s[oc * 8];
            const ulonglong2* wrr = (const ulonglong2*)&w1s[(16 + oc) * 8];
            #pragma unroll
            for (int q = 0; q < 4; ++q) {
                const ulonglong2 wl = wlr[q];         // LDS.128 broadcast
                const ulonglong2 wr = wrr[q];
                #pragma unroll
                for (int i = 0; i < ITEMS; ++i) {
                    hid[i][2 * q]     = ffma2(vl[i], wl.x, ffma2(vr[i], wr.x, hid[i][2 * q]));
                    hid[i][2 * q + 1] = ffma2(vl[i], wl.y, ffma2(vr[i], wr.y, hid[i][2 * q + 1]));
                }
            }
        }
    } // xp dies here

    // ---- logits + softmax(2): j outer so w2 LDS amortizes over items ----
    u64 lacc[ITEMS];
    {
        const u64 b2v = cW.b2[0];
        #pragma unroll
        for (int i = 0; i < ITEMS; ++i) lacc[i] = b2v;
        const ulonglong2* w2q = (const ulonglong2*)w2s;
        #pragma unroll
        for (int j = 0; j < 8; ++j) {
            const ulonglong2 wv = w2q[j];
            #pragma unroll
            for (int i = 0; i < ITEMS; ++i) {
                float h0, h1; upk(hid[i][j], h0, h1);
                h0 = fmaxf(h0, 0.f); h1 = fmaxf(h1, 0.f);
                lacc[i] = ffma2(pk(h0, h0), wv.x, lacc[i]);
                lacc[i] = ffma2(pk(h1, h1), wv.y, lacc[i]);
            }
        }
    }
    float a0v[ITEMS], a1v[ITEMS];
    #pragma unroll
    for (int i = 0; i < ITEMS; ++i) {
        float l0, l1; upk(lacc[i], l0, l1);
        const float e = __expf(l1 - l0);
        a0v[i] = 1.f / (1.f + e);
        a1v[i] = e * a0v[i];
    }

    // ---- gated residual + LayerNorm(16) + stores (x reloaded via LDS.128) ----
    #pragma unroll
    for (int i = 0; i < ITEMS; ++i) {
        const int tglob = tbase + r0 + i;
        const ulonglong2* xrow = (const ulonglong2*)&xs[ROWOFF(r0 + i + 2)];
        const u64 sp = pk(1.f + a0v[i], 1.f + a1v[i]);     // y = x * (1 + alpha_side)
        u64 yp[8];
        u64 sum = pk(0.f, 0.f);
        #pragma unroll
        for (int q = 0; q < 4; ++q) {
            const ulonglong2 v = xrow[q];
            yp[2 * q]     = fmul2(v.x, sp);
            yp[2 * q + 1] = fmul2(v.y, sp);
            sum = fadd2(sum, yp[2 * q]);
            sum = fadd2(sum, yp[2 * q + 1]);
        }
        float sL, sR; upk(sum, sL, sR);
        const float mu   = (sL + sR) * 0.0625f;
        const u64   nmup = pk(-mu, -mu);
        u64 var2 = pk(0.f, 0.f);
        u64 dp[8];
        #pragma unroll
        for (int c = 0; c < 8; ++c) { dp[c] = fadd2(yp[c], nmup); var2 = ffma2(dp[c], dp[c], var2); }
        float vL, vR; upk(var2, vL, vR);
        const float rs  = rsqrtf((vL + vR) * 0.0625f + 1e-5f);
        const u64   rsp = pk(rs, rs);

        float o[16];
        #pragma unroll
        for (int c = 0; c < 8; ++c) {
            const u64 op = ffma2(fmul2(dp[c], rsp), cW.g[c], cW.bb[c]);
            upk(op, o[c], o[c + 8]);
        }

        float4* outX = (float4*)(out + ((size_t)b * T_ + tglob) * 16);
        outX[0] = make_float4(o[0],  o[1],  o[2],  o[3]);
        outX[1] = make_float4(o[4],  o[5],  o[6],  o[7]);
        outX[2] = make_float4(o[8],  o[9],  o[10], o[11]);
        outX[3] = make_float4(o[12], o[13], o[14], o[15]);
        float2* outA = (float2*)(out + (size_t)B_ * T_ * 16 + ((size_t)b * T_ + tglob) * 2);
        *outA = make_float2(a0v[i], a1v[i]);
    }
}

extern "C" void kernel_launch(void* const* d_in, const int* in_sizes, int n_in,
                              void* d_out, int out_size)
{
    const float* x      = (const float*)d_in[0];
    const float* conv_w = (const float*)d_in[1];
    const float* conv_b = (const float*)d_in[2];
    const float* w1     = (const float*)d_in[3];
    const float* b1     = (const float*)d_in[4];
    const float* w2     = (const float*)d_in[5];
    const float* b2     = (const float*)d_in[6];
    const float* ln_g   = (const float*)d_in[7];
    const float* ln_b   = (const float*)d_in[8];

    // 1) pack weights into a device staging struct
    prep_kernel<<<1, 128>>>(conv_w, conv_b, w1, b1, w2, b2, ln_g, ln_b);

    // 2) D2D copy staging -> __constant__ (async, graph-capturable memcpy node)
    void* stage_ptr = nullptr;
    cudaGetSymbolAddress(&stage_ptr, dStage);
    cudaMemcpyToSymbolAsync(cW, stage_ptr, sizeof(Wts), 0, cudaMemcpyDeviceToDevice, 0);

    // 3) main kernel
    dim3 grid(T_ / TILE, B_);
    bimanual_kernel<<<grid, THREADS>>>(x, (float*)d_out);
}

// round 9
// speedup vs baseline: 1.0867x; 1.0867x over previous
#include <cuda_runtime.h>

#define B_      512
#define T_      4096
#define THREADS 128
#define ITEMS   2
#define TILE    (THREADS * ITEMS)   // 256 -> grid.x = 16 exact
// row offset in u64: 10r + 2*(r/2). All rows 16B-aligned; lane stride (r0=2*tid)
// = 22 u64 = 44 words == 12 (mod 32) -> LDS.128 8-lane phases conflict-free.
#define ROWOFF(r) ((r) * 10 + ((((r) >> 1)) << 1))

typedef unsigned long long u64;

// ---- packed f32x2 helpers (PTX-only path on sm_103a; ptxas won't auto-fuse) ----
__device__ __forceinline__ u64 pk(float lo, float hi) {
    u64 r; asm("mov.b64 %0,{%1,%2};" : "=l"(r) : "f"(lo), "f"(hi)); return r;
}
__device__ __forceinline__ void upk(u64 v, float& lo, float& hi) {
    asm("mov.b64 {%0,%1},%2;" : "=f"(lo), "=f"(hi) : "l"(v));
}
__device__ __forceinline__ u64 ffma2(u64 a, u64 b, u64 c) {
    u64 d; asm("fma.rn.f32x2 %0,%1,%2,%3;" : "=l"(d) : "l"(a), "l"(b), "l"(c)); return d;
}
__device__ __forceinline__ u64 fmul2(u64 a, u64 b) {
    u64 d; asm("mul.rn.f32x2 %0,%1,%2;" : "=l"(d) : "l"(a), "l"(b)); return d;
}
__device__ __forceinline__ u64 fadd2(u64 a, u64 b) {
    u64 d; asm("add.rn.f32x2 %0,%1,%2;" : "=l"(d) : "l"(a), "l"(b)); return d;
}

// ---- weights, pre-packed for f32x2 ----
// conv weights, w1 (oc 0..7), w2, biases, LN -> __constant__ (LDC port)
// w1 (oc 8..15, both L/R rows)           -> smem (LDS port), staged via dStage
struct __align__(16) Wts {
    u64 cw[384];   // conv weights (w,w) pairs, [oc][k][ic]
    u64 w1[256];   // w1 as hidden-output pairs: w1[f][j] = (w1[f,2j], w1[f,2j+1])
    u64 w2[16];    // w2 row pairs (w2[h][0], w2[h][1])
    u64 cb[16];    // conv bias (b,b)
    u64 b1[8];     // b1 output pairs
    u64 b2[2];     // (b2[0], b2[1]) + pad
    u64 g[8];      // ln gamma packed (c, c+8)
    u64 bb[8];     // ln beta  packed (c, c+8)
};
__constant__ Wts cW;
__device__   Wts dStage;

__global__ void prep_kernel(const float* __restrict__ conv_w, const float* __restrict__ conv_b,
                            const float* __restrict__ w1,     const float* __restrict__ b1,
                            const float* __restrict__ w2,     const float* __restrict__ b2,
                            const float* __restrict__ ln_g,   const float* __restrict__ ln_b)
{
    const int tid = threadIdx.x;
    for (int j = tid; j < 384; j += 128) {
        const int oc = j / 24, r = j % 24, ic = r / 3, k = r % 3;   // conv_w is (oc, ic, k)
        const float w = conv_w[j];
        dStage.cw[oc * 24 + k * 8 + ic] = pk(w, w);
    }
    for (int j = tid; j < 256; j += 128) {
        const int f = j / 8, q = j % 8;
        dStage.w1[j] = pk(w1[f * 16 + 2 * q], w1[f * 16 + 2 * q + 1]);
    }
    if (tid < 16) dStage.w2[tid] = pk(w2[2 * tid], w2[2 * tid + 1]);
    if (tid < 16) dStage.cb[tid] = pk(conv_b[tid], conv_b[tid]);
    if (tid < 8)  dStage.b1[tid] = pk(b1[2 * tid], b1[2 * tid + 1]);
    if (tid == 0) { dStage.b2[0] = pk(b2[0], b2[1]); dStage.b2[1] = 0ull; }
    if (tid < 8)  dStage.g[tid]  = pk(ln_g[tid], ln_g[tid + 8]);
    if (tid < 8)  dStage.bb[tid] = pk(ln_b[tid], ln_b[tid + 8]);
}

__global__ __launch_bounds__(THREADS, 4)
void bimanual_kernel(const float* __restrict__ x, float* __restrict__ out)
{
    __shared__ __align__(16) u64 xs[ROWOFF(TILE + 2)];   // 16B-aligned staggered x tile
    // w1 rows for oc 8..15 only: [0..63] = L-rows (oc-8)*8+j, [64..127] = R-rows
    __shared__ __align__(16) u64 w1s[128];

    const int tid   = threadIdx.x;
    const int b     = blockIdx.y;
    const int tbase = blockIdx.x * TILE;

    // ---- stage x tile (TILE + 2 halo rows; t<0 rows are the conv zero-padding) ----
    for (int tt = tid; tt < TILE + 2; tt += THREADS) {
        const int t = tbase - 2 + tt;
        ulonglong2* row = (ulonglong2*)&xs[ROWOFF(tt)];
        if (t >= 0) {
            const float4* p = (const float4*)(x + ((size_t)b * T_ + t) * 16);
            float4 a = p[0], bq = p[1], c = p[2], d = p[3];
            row[0] = make_ulonglong2(pk(a.x,  c.x), pk(a.y,  c.y));
            row[1] = make_ulonglong2(pk(a.z,  c.z), pk(a.w,  c.w));
            row[2] = make_ulonglong2(pk(bq.x, d.x), pk(bq.y, d.y));
            row[3] = make_ulonglong2(pk(bq.z, d.z), pk(bq.w, d.w));
        } else {
            row[0] = make_ulonglong2(0ull, 0ull);
            row[1] = make_ulonglong2(0ull, 0ull);
            row[2] = make_ulonglong2(0ull, 0ull);
            row[3] = make_ulonglong2(0ull, 0ull);
        }
    }
    // ---- stage w1 smem half: L-rows 8..15 -> [0..63], R-rows 24..31 -> [64..127] ----
    if (tid < 64)                w1s[tid]      = dStage.w1[64 + tid];        // oc 8..15 (L)
    else if (tid < 128)          w1s[tid]      = dStage.w1[192 + (tid - 64)]; // oc 24..31 (R)
    __syncthreads();

    // ---- per-thread: ITEMS consecutive elements, window rows r0 .. r0+ITEMS+1 ----
    const int r0 = tid * ITEMS;

    // hidden accumulators: 8 packed output-pairs per element
    u64 hid[ITEMS][8];
    #pragma unroll
    for (int j = 0; j < 8; ++j) {
        const u64 bj = cW.b1[j];
        #pragma unroll
        for (int i = 0; i < ITEMS; ++i) hid[i][j] = bj;
    }

    // Scope the x window so it is dead after the conv loop (register pressure).
    {
        u64 xp[ITEMS + 2][8];
        #pragma unroll
        for (int r = 0; r < ITEMS + 2; ++r) {
            const ulonglong2* row = (const ulonglong2*)&xs[ROWOFF(r0 + r)];
            #pragma unroll
            for (int q = 0; q < 4; ++q) {           // 4x LDS.128 per row, conflict-free
                const ulonglong2 v = row[q];
                xp[r][2 * q] = v.x; xp[r][2 * q + 1] = v.y;
            }
        }

        // ---- fused conv(+ReLU) -> rank-1 MLP update ----
        // conv weights via LDC; w1 rows: oc 0..7 via LDC, oc 8..15 via LDS (port split)
        #pragma unroll
        for (int oc = 0; oc < 16; ++oc) {
            u64 acc[ITEMS];
            {
                const u64 cb = cW.cb[oc];
                #pragma unroll
                for (int i = 0; i < ITEMS; ++i) acc[i] = cb;
            }
            #pragma unroll
            for (int k = 0; k < 3; ++k) {
                const ulonglong2* wp = (const ulonglong2*)&cW.cw[oc * 24 + k * 8];
                #pragma unroll
                for (int q = 0; q < 4; ++q) {
                    const ulonglong2 wv = wp[q];      // LDC.128 = 2 packed weight pairs
                    #pragma unroll
                    for (int i = 0; i < ITEMS; ++i)
                        acc[i] = ffma2(xp[i + k][2 * q], wv.x, acc[i]);
                    #pragma unroll
                    for (int i = 0; i < ITEMS; ++i)
                        acc[i] = ffma2(xp[i + k][2 * q + 1], wv.y, acc[i]);
                }
            }
            // ReLU + broadcast-splat per element
            u64 vl[ITEMS], vr[ITEMS];
            #pragma unroll
            for (int i = 0; i < ITEMS; ++i) {
                float hl, hr; upk(acc[i], hl, hr);
                hl = fmaxf(hl, 0.f); hr = fmaxf(hr, 0.f);
                vl[i] = pk(hl, hl); vr[i] = pk(hr, hr);
            }
            // rank-1 update of hidden accs: hid += hl*w1[oc,:] + hr*w1[16+oc,:]
            #pragma unroll
            for (int q = 0; q < 4; ++q) {
                ulonglong2 wl, wr;
                if (oc < 8) {                          // constant port (LDC.128)
                    wl = ((const ulonglong2*)&cW.w1[oc * 8])[q];
                    wr = ((const ulonglong2*)&cW.w1[(16 + oc) * 8])[q];
                } else {                               // shared port (LDS.128 broadcast)
                    wl = ((const ulonglong2*)&w1s[(oc - 8) * 8])[q];
                    wr = ((const ulonglong2*)&w1s[64 + (oc - 8) * 8])[q];
                }
                #pragma unroll
                for (int i = 0; i < ITEMS; ++i) {
                    hid[i][2 * q]     = ffma2(vl[i], wl.x, ffma2(vr[i], wr.x, hid[i][2 * q]));
                    hid[i][2 * q + 1] = ffma2(vl[i], wl.y, ffma2(vr[i], wr.y, hid[i][2 * q + 1]));
                }
            }
        }
    } // xp dies here

    // ---- logits + softmax(2): j outer so w2 LDC amortizes over items ----
    u64 lacc[ITEMS];
    {
        const u64 b2v = cW.b2[0];
        #pragma unroll
        for (int i = 0; i < ITEMS; ++i) lacc[i] = b2v;
        const ulonglong2* w2q = (const ulonglong2*)cW.w2;
        #pragma unroll
        for (int j = 0; j < 8; ++j) {
            const ulonglong2 wv = w2q[j];
            #pragma unroll
            for (int i = 0; i < ITEMS; ++i) {
                float h0, h1; upk(hid[i][j], h0, h1);
                h0 = fmaxf(h0, 0.f); h1 = fmaxf(h1, 0.f);
                lacc[i] = ffma2(pk(h0, h0), wv.x, lacc[i]);
                lacc[i] = ffma2(pk(h1, h1), wv.y, lacc[i]);
            }
        }
    }
    float a0v[ITEMS], a1v[ITEMS];
    #pragma unroll
    for (int i = 0; i < ITEMS; ++i) {
        float l0, l1; upk(lacc[i], l0, l1);
        const float e = __expf(l1 - l0);
        a0v[i] = 1.f / (1.f + e);
        a1v[i] = e * a0v[i];
    }

    // ---- gated residual + LayerNorm(16) + stores (x reloaded via LDS.128) ----
    #pragma unroll
    for (int i = 0; i < ITEMS; ++i) {
        const int tglob = tbase + r0 + i;
        const ulonglong2* xrow = (const ulonglong2*)&xs[ROWOFF(r0 + i + 2)];
        const u64 sp = pk(1.f + a0v[i], 1.f + a1v[i]);     // y = x * (1 + alpha_side)
        u64 yp[8];
        u64 sum = pk(0.f, 0.f);
        #pragma unroll
        for (int q = 0; q < 4; ++q) {
            const ulonglong2 v = xrow[q];
            yp[2 * q]     = fmul2(v.x, sp);
            yp[2 * q + 1] = fmul2(v.y, sp);
            sum = fadd2(sum, yp[2 * q]);
            sum = fadd2(sum, yp[2 * q + 1]);
        }
        float sL, sR; upk(sum, sL, sR);
        const float mu   = (sL + sR) * 0.0625f;
        const u64   nmup = pk(-mu, -mu);
        u64 var2 = pk(0.f, 0.f);
        u64 dp[8];
        #pragma unroll
        for (int c = 0; c < 8; ++c) { dp[c] = fadd2(yp[c], nmup); var2 = ffma2(dp[c], dp[c], var2); }
        float vL, vR; upk(var2, vL, vR);
        const float rs  = rsqrtf((vL + vR) * 0.0625f + 1e-5f);
        const u64   rsp = pk(rs, rs);

        float o[16];
        #pragma unroll
        for (int c = 0; c < 8; ++c) {
            const u64 op = ffma2(fmul2(dp[c], rsp), cW.g[c], cW.bb[c]);
            upk(op, o[c], o[c + 8]);
        }

        float4* outX = (float4*)(out + ((size_t)b * T_ + tglob) * 16);
        outX[0] = make_float4(o[0],  o[1],  o[2],  o[3]);
        outX[1] = make_float4(o[4],  o[5],  o[6],  o[7]);
        outX[2] = make_float4(o[8],  o[9],  o[10], o[11]);
        outX[3] = make_float4(o[12], o[13], o[14], o[15]);
        float2* outA = (float2*)(out + (size_t)B_ * T_ * 16 + ((size_t)b * T_ + tglob) * 2);
        *outA = make_float2(a0v[i], a1v[i]);
    }
}

extern "C" void kernel_launch(void* const* d_in, const int* in_sizes, int n_in,
                              void* d_out, int out_size)
{
    const float* x      = (const float*)d_in[0];
    const float* conv_w = (const float*)d_in[1];
    const float* conv_b = (const float*)d_in[2];
    const float* w1     = (const float*)d_in[3];
    const float* b1     = (const float*)d_in[4];
    const float* w2     = (const float*)d_in[5];
    const float* b2     = (const float*)d_in[6];
    const float* ln_g   = (const float*)d_in[7];
    const float* ln_b   = (const float*)d_in[8];

    // 1) pack weights into a device staging struct
    prep_kernel<<<1, 128>>>(conv_w, conv_b, w1, b1, w2, b2, ln_g, ln_b);

    // 2) D2D copy staging -> __constant__ (async, graph-capturable memcpy node)
    void* stage_ptr = nullptr;
    cudaGetSymbolAddress(&stage_ptr, dStage);
    cudaMemcpyToSymbolAsync(cW, stage_ptr, sizeof(Wts), 0, cudaMemcpyDeviceToDevice, 0);

    // 3) main kernel
    dim3 grid(T_ / TILE, B_);
    bimanual_kernel<<<grid, THREADS>>>(x, (float*)d_out);
}

// round 10
// speedup vs baseline: 1.1430x; 1.0518x over previous
#include <cuda_runtime.h>

#define B_      512
#define T_      4096
#define THREADS 128
#define ITEMS   2
#define TILE    (THREADS * ITEMS)   // 256 -> grid.x = 16 exact
// row offset in u64: 10r + 2*(r/2). All rows 16B-aligned; lane stride (r0=2*tid)
// = 22 u64 = 44 words == 12 (mod 32) -> LDS.128 8-lane phases conflict-free.
#define ROWOFF(r) ((r) * 10 + ((((r) >> 1)) << 1))

typedef unsigned long long u64;

// ---- packed f32x2 helpers (PTX-only path on sm_103a; ptxas won't auto-fuse) ----
__device__ __forceinline__ u64 pk(float lo, float hi) {
    u64 r; asm("mov.b64 %0,{%1,%2};" : "=l"(r) : "f"(lo), "f"(hi)); return r;
}
__device__ __forceinline__ void upk(u64 v, float& lo, float& hi) {
    asm("mov.b64 {%0,%1},%2;" : "=f"(lo), "=f"(hi) : "l"(v));
}
__device__ __forceinline__ u64 ffma2(u64 a, u64 b, u64 c) {
    u64 d; asm("fma.rn.f32x2 %0,%1,%2,%3;" : "=l"(d) : "l"(a), "l"(b), "l"(c)); return d;
}
__device__ __forceinline__ u64 fmul2(u64 a, u64 b) {
    u64 d; asm("mul.rn.f32x2 %0,%1,%2;" : "=l"(d) : "l"(a), "l"(b)); return d;
}
__device__ __forceinline__ u64 fadd2(u64 a, u64 b) {
    u64 d; asm("add.rn.f32x2 %0,%1,%2;" : "=l"(d) : "l"(a), "l"(b)); return d;
}

// ---- ALL weights, pre-packed for f32x2, in constant memory (LDC port only).
// R7-R9 established: moving any weight stream to LDS regresses (L1 is the
// scarce pipe; LDC overlaps under the FMA floor).
struct __align__(16) Wts {
    u64 cw[384];   // conv weights (w,w) pairs, [oc][k][ic]
    u64 w1[256];   // w1 as hidden-output pairs: w1[f][j] = (w1[f,2j], w1[f,2j+1])
    u64 w2[16];    // w2 row pairs (w2[h][0], w2[h][1])
    u64 cb[16];    // conv bias (b,b)
    u64 b1[8];     // b1 output pairs
    u64 b2[2];     // (b2[0], b2[1]) + pad
    u64 g[8];      // ln gamma packed (c, c+8)
    u64 bb[8];     // ln beta  packed (c, c+8)
};
__constant__ Wts cW;
__device__   Wts dStage;

__global__ void prep_kernel(const float* __restrict__ conv_w, const float* __restrict__ conv_b,
                            const float* __restrict__ w1,     const float* __restrict__ b1,
                            const float* __restrict__ w2,     const float* __restrict__ b2,
                            const float* __restrict__ ln_g,   const float* __restrict__ ln_b)
{
    const int tid = threadIdx.x;
    for (int j = tid; j < 384; j += 128) {
        const int oc = j / 24, r = j % 24, ic = r / 3, k = r % 3;   // conv_w is (oc, ic, k)
        const float w = conv_w[j];
        dStage.cw[oc * 24 + k * 8 + ic] = pk(w, w);
    }
    for (int j = tid; j < 256; j += 128) {
        const int f = j / 8, q = j % 8;
        dStage.w1[j] = pk(w1[f * 16 + 2 * q], w1[f * 16 + 2 * q + 1]);
    }
    if (tid < 16) dStage.w2[tid] = pk(w2[2 * tid], w2[2 * tid + 1]);
    if (tid < 16) dStage.cb[tid] = pk(conv_b[tid], conv_b[tid]);
    if (tid < 8)  dStage.b1[tid] = pk(b1[2 * tid], b1[2 * tid + 1]);
    if (tid == 0) { dStage.b2[0] = pk(b2[0], b2[1]); dStage.b2[1] = 0ull; }
    if (tid < 8)  dStage.g[tid]  = pk(ln_g[tid], ln_g[tid + 8]);
    if (tid < 8)  dStage.bb[tid] = pk(ln_b[tid], ln_b[tid + 8]);
}

__global__ __launch_bounds__(THREADS, 4)
void bimanual_kernel(const float* __restrict__ x, float* __restrict__ out)
{
    __shared__ __align__(16) u64 xs[ROWOFF(TILE + 2)];   // 16B-aligned staggered x tile

    const int tid   = threadIdx.x;
    const int b     = blockIdx.y;
    const int tbase = blockIdx.x * TILE;

    // ---- stage x tile (TILE + 2 halo rows; t<0 rows are the conv zero-padding) ----
    for (int tt = tid; tt < TILE + 2; tt += THREADS) {
        const int t = tbase - 2 + tt;
        ulonglong2* row = (ulonglong2*)&xs[ROWOFF(tt)];
        if (t >= 0) {
            const float4* p = (const float4*)(x + ((size_t)b * T_ + t) * 16);
            float4 a = p[0], bq = p[1], c = p[2], d = p[3];
            row[0] = make_ulonglong2(pk(a.x,  c.x), pk(a.y,  c.y));
            row[1] = make_ulonglong2(pk(a.z,  c.z), pk(a.w,  c.w));
            row[2] = make_ulonglong2(pk(bq.x, d.x), pk(bq.y, d.y));
            row[3] = make_ulonglong2(pk(bq.z, d.z), pk(bq.w, d.w));
        } else {
            row[0] = make_ulonglong2(0ull, 0ull);
            row[1] = make_ulonglong2(0ull, 0ull);
            row[2] = make_ulonglong2(0ull, 0ull);
            row[3] = make_ulonglong2(0ull, 0ull);
        }
    }
    __syncthreads();

    // ---- per-thread: ITEMS consecutive elements, window rows r0 .. r0+ITEMS+1 ----
    const int r0 = tid * ITEMS;

    // hidden accumulators: 8 packed output-pairs per element
    u64 hid[ITEMS][8];
    #pragma unroll
    for (int j = 0; j < 8; ++j) {
        const u64 bj = cW.b1[j];
        #pragma unroll
        for (int i = 0; i < ITEMS; ++i) hid[i][j] = bj;
    }

    // Scope the x window so it is dead after the conv loop (register pressure).
    {
        u64 xp[ITEMS + 2][8];
        #pragma unroll
        for (int r = 0; r < ITEMS + 2; ++r) {
            const ulonglong2* row = (const ulonglong2*)&xs[ROWOFF(r0 + r)];
            #pragma unroll
            for (int q = 0; q < 4; ++q) {           // 4x LDS.128 per row, conflict-free
                const ulonglong2 v = row[q];
                xp[r][2 * q] = v.x; xp[r][2 * q + 1] = v.y;
            }
        }

        // ---- fused conv(+ReLU) -> rank-1 MLP update; all weights via LDC ----
        #pragma unroll
        for (int oc = 0; oc < 16; ++oc) {
            u64 acc[ITEMS];
            {
                const u64 cb = cW.cb[oc];
                #pragma unroll
                for (int i = 0; i < ITEMS; ++i) acc[i] = cb;
            }
            #pragma unroll
            for (int k = 0; k < 3; ++k) {
                const ulonglong2* wp = (const ulonglong2*)&cW.cw[oc * 24 + k * 8];
                #pragma unroll
                for (int q = 0; q < 4; ++q) {
                    const ulonglong2 wv = wp[q];      // LDC.128 = 2 packed weight pairs
                    #pragma unroll
                    for (int i = 0; i < ITEMS; ++i)
                        acc[i] = ffma2(xp[i + k][2 * q], wv.x, acc[i]);
                    #pragma unroll
                    for (int i = 0; i < ITEMS; ++i)
                        acc[i] = ffma2(xp[i + k][2 * q + 1], wv.y, acc[i]);
                }
            }
            // ReLU + splat, then rank-1 update: hid += hl*w1[oc,:] + hr*w1[16+oc,:]
            u64 vl[ITEMS], vr[ITEMS];
            #pragma unroll
            for (int i = 0; i < ITEMS; ++i) {
                float hl, hr; upk(acc[i], hl, hr);
                hl = fmaxf(hl, 0.f); hr = fmaxf(hr, 0.f);
                vl[i] = pk(hl, hl); vr[i] = pk(hr, hr);
            }
            const ulonglong2* wlr = (const ulonglong2*)&cW.w1[oc * 8];
            const ulonglong2* wrr = (const ulonglong2*)&cW.w1[(16 + oc) * 8];
            #pragma unroll
            for (int q = 0; q < 4; ++q) {
                const ulonglong2 wl = wlr[q];         // LDC.128
                const ulonglong2 wr = wrr[q];
                #pragma unroll
                for (int i = 0; i < ITEMS; ++i) {
                    hid[i][2 * q]     = ffma2(vl[i], wl.x, ffma2(vr[i], wr.x, hid[i][2 * q]));
                    hid[i][2 * q + 1] = ffma2(vl[i], wl.y, ffma2(vr[i], wr.y, hid[i][2 * q + 1]));
                }
            }
        }
    } // xp dies here

    // ---- logits + softmax(2): j outer so w2 LDC amortizes over items ----
    u64 lacc[ITEMS];
    {
        const u64 b2v = cW.b2[0];
        #pragma unroll
        for (int i = 0; i < ITEMS; ++i) lacc[i] = b2v;
        const ulonglong2* w2q = (const ulonglong2*)cW.w2;
        #pragma unroll
        for (int j = 0; j < 8; ++j) {
            const ulonglong2 wv = w2q[j];
            #pragma unroll
            for (int i = 0; i < ITEMS; ++i) {
                float h0, h1; upk(hid[i][j], h0, h1);
                h0 = fmaxf(h0, 0.f); h1 = fmaxf(h1, 0.f);
                lacc[i] = ffma2(pk(h0, h0), wv.x, lacc[i]);
                lacc[i] = ffma2(pk(h1, h1), wv.y, lacc[i]);
            }
        }
    }
    float a0v[ITEMS], a1v[ITEMS];
    #pragma unroll
    for (int i = 0; i < ITEMS; ++i) {
        float l0, l1; upk(lacc[i], l0, l1);
        const float e = __expf(l1 - l0);
        a0v[i] = 1.f / (1.f + e);
        a1v[i] = e * a0v[i];
    }

    // ---- gated residual + LayerNorm(16) + stores (x reloaded via LDS.128) ----
    #pragma unroll
    for (int i = 0; i < ITEMS; ++i) {
        const int tglob = tbase + r0 + i;
        const ulonglong2* xrow = (const ulonglong2*)&xs[ROWOFF(r0 + i + 2)];
        const u64 sp = pk(1.f + a0v[i], 1.f + a1v[i]);     // y = x * (1 + alpha_side)
        u64 yp[8];
        u64 sum = pk(0.f, 0.f);
        #pragma unroll
        for (int q = 0; q < 4; ++q) {
            const ulonglong2 v = xrow[q];
            yp[2 * q]     = fmul2(v.x, sp);
            yp[2 * q + 1] = fmul2(v.y, sp);
            sum = fadd2(sum, yp[2 * q]);
            sum = fadd2(sum, yp[2 * q + 1]);
        }
        float sL, sR; upk(sum, sL, sR);
        const float mu   = (sL + sR) * 0.0625f;
        const u64   nmup = pk(-mu, -mu);
        u64 var2 = pk(0.f, 0.f);
        u64 dp[8];
        #pragma unroll
        for (int c = 0; c < 8; ++c) { dp[c] = fadd2(yp[c], nmup); var2 = ffma2(dp[c], dp[c], var2); }
        float vL, vR; upk(var2, vL, vR);
        const float rs  = rsqrtf((vL + vR) * 0.0625f + 1e-5f);
        const u64   rsp = pk(rs, rs);

        float o[16];
        #pragma unroll
        for (int c = 0; c < 8; ++c) {
            const u64 op = ffma2(fmul2(dp[c], rsp), cW.g[c], cW.bb[c]);
            upk(op, o[c], o[c + 8]);
        }

        float4* outX = (float4*)(out + ((size_t)b * T_ + tglob) * 16);
        outX[0] = make_float4(o[0],  o[1],  o[2],  o[3]);
        outX[1] = make_float4(o[4],  o[5],  o[6],  o[7]);
        outX[2] = make_float4(o[8],  o[9],  o[10], o[11]);
        outX[3] = make_float4(o[12], o[13], o[14], o[15]);
        float2* outA = (float2*)(out + (size_t)B_ * T_ * 16 + ((size_t)b * T_ + tglob) * 2);
        *outA = make_float2(a0v[i], a1v[i]);
    }
}

extern "C" void kernel_launch(void* const* d_in, const int* in_sizes, int n_in,
                              void* d_out, int out_size)
{
    const float* x      = (const float*)d_in[0];
    const float* conv_w = (const float*)d_in[1];
    const float* conv_b = (const float*)d_in[2];
    const float* w1     = (const float*)d_in[3];
    const float* b1     = (const float*)d_in[4];
    const float* w2     = (const float*)d_in[5];
    const float* b2     = (const float*)d_in[6];
    const float* ln_g   = (const float*)d_in[7];
    const float* ln_b   = (const float*)d_in[8];

    // 1) pack weights into a device staging struct
    prep_kernel<<<1, 128>>>(conv_w, conv_b, w1, b1, w2, b2, ln_g, ln_b);

    // 2) D2D copy staging -> __constant__ (async, graph-capturable memcpy node)
    void* stage_ptr = nullptr;
    cudaGetSymbolAddress(&stage_ptr, dStage);
    cudaMemcpyToSymbolAsync(cW, stage_ptr, sizeof(Wts), 0, cudaMemcpyDeviceToDevice, 0);

    // 3) main kernel
    dim3 grid(T_ / TILE, B_);
    bimanual_kernel<<<grid, THREADS>>>(x, (float*)d_out);
}

// round 11
// speedup vs baseline: 1.3047x; 1.1415x over previous
#include <cuda_runtime.h>

#define B_      512
#define T_      4096
#define THREADS 128
#define ITEMS   2
#define TILE    (THREADS * ITEMS)   // 256 -> grid.x = 16 exact
// row offset in u64: 10r + 2*(r/2). All rows 16B-aligned; lane stride (r0=2*tid)
// = 22 u64 = 44 words == 12 (mod 32) -> LDS.128 8-lane phases conflict-free.
#define ROWOFF(r) ((r) * 10 + ((((r) >> 1)) << 1))

typedef unsigned long long u64;

// ---- packed f32x2 helpers (PTX-only path on sm_103a; ptxas won't auto-fuse) ----
__device__ __forceinline__ u64 pk(float lo, float hi) {
    u64 r; asm("mov.b64 %0,{%1,%2};" : "=l"(r) : "f"(lo), "f"(hi)); return r;
}
__device__ __forceinline__ void upk(u64 v, float& lo, float& hi) {
    asm("mov.b64 {%0,%1},%2;" : "=f"(lo), "=f"(hi) : "l"(v));
}
__device__ __forceinline__ u64 ffma2(u64 a, u64 b, u64 c) {
    u64 d; asm("fma.rn.f32x2 %0,%1,%2,%3;" : "=l"(d) : "l"(a), "l"(b), "l"(c)); return d;
}
__device__ __forceinline__ u64 fmul2(u64 a, u64 b) {
    u64 d; asm("mul.rn.f32x2 %0,%1,%2;" : "=l"(d) : "l"(a), "l"(b)); return d;
}
__device__ __forceinline__ u64 fadd2(u64 a, u64 b) {
    u64 d; asm("add.rn.f32x2 %0,%1,%2;" : "=l"(d) : "l"(a), "l"(b)); return d;
}

// ---- ALL weights in constant memory (LDC port; R7-R9: LDS offload regresses).
// Conv weights now stored as GENUINE ic-pair packs (w[ic],w[ic+1]) — x stays in
// natural channel order, so no duplicated (w,w) pairs: conv LDC traffic halves.
struct __align__(16) Wts {
    u64 cwn[192];  // conv weights [oc][k][c]: pair c = (w[oc,2c,k], w[oc,2c+1,k])
    u64 w1[256];   // w1 as hidden-output pairs: w1[f][j] = (w1[f,2j], w1[f,2j+1])
    u64 w2[16];    // w2 row pairs (w2[h][0], w2[h][1])
    u64 cbp[16];   // conv bias as (cb, 0) pairs (folded into pairwise conv acc)
    u64 b1[8];     // b1 output pairs
    u64 b2[2];     // (b2[0], b2[1]) + pad
    u64 g[8];      // ln gamma natural pairs (2c, 2c+1)
    u64 bb[8];     // ln beta  natural pairs (2c, 2c+1)
};
__constant__ Wts cW;
__device__   Wts dStage;

__global__ void prep_kernel(const float* __restrict__ conv_w, const float* __restrict__ conv_b,
                            const float* __restrict__ w1,     const float* __restrict__ b1,
                            const float* __restrict__ w2,     const float* __restrict__ b2,
                            const float* __restrict__ ln_g,   const float* __restrict__ ln_b)
{
    const int tid = threadIdx.x;
    // conv_w is (oc, ic, k): idx = oc*24 + ic*3 + k
    for (int j = tid; j < 192; j += 128) {
        const int oc = j / 12, r = j % 12, k = r / 4, c = r % 4;
        dStage.cwn[oc * 12 + k * 4 + c] =
            pk(conv_w[oc * 24 + (2 * c) * 3 + k], conv_w[oc * 24 + (2 * c + 1) * 3 + k]);
    }
    for (int j = tid; j < 256; j += 128) {
        const int f = j / 8, q = j % 8;
        dStage.w1[j] = pk(w1[f * 16 + 2 * q], w1[f * 16 + 2 * q + 1]);
    }
    if (tid < 16) dStage.w2[tid]  = pk(w2[2 * tid], w2[2 * tid + 1]);
    if (tid < 16) dStage.cbp[tid] = pk(conv_b[tid], 0.f);
    if (tid < 8)  dStage.b1[tid]  = pk(b1[2 * tid], b1[2 * tid + 1]);
    if (tid == 0) { dStage.b2[0] = pk(b2[0], b2[1]); dStage.b2[1] = 0ull; }
    if (tid < 8)  dStage.g[tid]   = pk(ln_g[2 * tid], ln_g[2 * tid + 1]);
    if (tid < 8)  dStage.bb[tid]  = pk(ln_b[2 * tid], ln_b[2 * tid + 1]);
}

__global__ __launch_bounds__(THREADS, 4)
void bimanual_kernel(const float* __restrict__ x, float* __restrict__ out)
{
    __shared__ __align__(16) u64 xs[ROWOFF(TILE + 2)];   // natural-order x tile (staggered)

    const int tid   = threadIdx.x;
    const int b     = blockIdx.y;
    const int tbase = blockIdx.x * TILE;

    // ---- stage x tile: straight 4x16B copy per row (natural channel order) ----
    for (int tt = tid; tt < TILE + 2; tt += THREADS) {
        const int t = tbase - 2 + tt;
        ulonglong2* row = (ulonglong2*)&xs[ROWOFF(tt)];
        if (t >= 0) {
            const ulonglong2* p = (const ulonglong2*)(x + ((size_t)b * T_ + t) * 16);
            row[0] = p[0]; row[1] = p[1]; row[2] = p[2]; row[3] = p[3];
        } else {
            row[0] = make_ulonglong2(0ull, 0ull);
            row[1] = make_ulonglong2(0ull, 0ull);
            row[2] = make_ulonglong2(0ull, 0ull);
            row[3] = make_ulonglong2(0ull, 0ull);
        }
    }
    __syncthreads();

    // ---- per-thread: ITEMS consecutive elements, window rows r0 .. r0+ITEMS+1 ----
    const int r0 = tid * ITEMS;

    // hidden accumulators: 8 packed output-pairs per element
    u64 hid[ITEMS][8];
    #pragma unroll
    for (int j = 0; j < 8; ++j) {
        const u64 bj = cW.b1[j];
        #pragma unroll
        for (int i = 0; i < ITEMS; ++i) hid[i][j] = bj;
    }

    // Scope the x window so it is dead after the conv loop (register pressure).
    {
        // xp[r][0..3] = L channels (ic pairs), xp[r][4..7] = R channels (ic pairs)
        u64 xp[ITEMS + 2][8];
        #pragma unroll
        for (int r = 0; r < ITEMS + 2; ++r) {
            const ulonglong2* row = (const ulonglong2*)&xs[ROWOFF(r0 + r)];
            #pragma unroll
            for (int q = 0; q < 4; ++q) {           // 4x LDS.128 per row, conflict-free
                const ulonglong2 v = row[q];
                xp[r][2 * q] = v.x; xp[r][2 * q + 1] = v.y;
            }
        }

        // ---- fused conv(+ReLU) -> rank-1 MLP update; per-stream ic-pair FFMA2,
        //      genuine (non-duplicated) conv weight pairs via LDC ----
        #pragma unroll
        for (int oc = 0; oc < 16; ++oc) {
            u64 aL[ITEMS], aR[ITEMS];
            {
                const u64 cb0 = cW.cbp[oc];          // (cb, 0): bias folds into lane-sum
                #pragma unroll
                for (int i = 0; i < ITEMS; ++i) { aL[i] = cb0; aR[i] = pk(0.f, 0.f); }
            }
            #pragma unroll
            for (int k = 0; k < 3; ++k) {
                const ulonglong2* wp = (const ulonglong2*)&cW.cwn[oc * 12 + k * 4];
                const ulonglong2 w01 = wp[0];        // LDC.128: ic-pairs 0-1
                const ulonglong2 w23 = wp[1];        // LDC.128: ic-pairs 2-3
                #pragma unroll
                for (int i = 0; i < ITEMS; ++i) {
                    aL[i] = ffma2(xp[i + k][0], w01.x, aL[i]);
                    aL[i] = ffma2(xp[i + k][1], w01.y, aL[i]);
                    aL[i] = ffma2(xp[i + k][2], w23.x, aL[i]);
                    aL[i] = ffma2(xp[i + k][3], w23.y, aL[i]);
                    aR[i] = ffma2(xp[i + k][4], w01.x, aR[i]);
                    aR[i] = ffma2(xp[i + k][5], w01.y, aR[i]);
                    aR[i] = ffma2(xp[i + k][6], w23.x, aR[i]);
                    aR[i] = ffma2(xp[i + k][7], w23.y, aR[i]);
                }
            }
            // horizontal lane-sum + bias(cb in aL.lo; add cb to R via scalar) + ReLU
            u64 vl[ITEMS], vr[ITEMS];
            {
                float cb; { float z; upk(cW.cbp[oc], cb, z); }
                #pragma unroll
                for (int i = 0; i < ITEMS; ++i) {
                    float l0, l1, rr0, rr1;
                    upk(aL[i], l0, l1); upk(aR[i], rr0, rr1);
                    const float hl = fmaxf(l0 + l1, 0.f);            // cb already in l0
                    const float hr = fmaxf(rr0 + rr1 + cb, 0.f);
                    vl[i] = pk(hl, hl); vr[i] = pk(hr, hr);
                }
            }
            // rank-1 update of hidden accs: hid += hl*w1[oc,:] + hr*w1[16+oc,:]
            const ulonglong2* wlr = (const ulonglong2*)&cW.w1[oc * 8];
            const ulonglong2* wrr = (const ulonglong2*)&cW.w1[(16 + oc) * 8];
            #pragma unroll
            for (int q = 0; q < 4; ++q) {
                const ulonglong2 wl = wlr[q];         // LDC.128
                const ulonglong2 wr = wrr[q];
                #pragma unroll
                for (int i = 0; i < ITEMS; ++i) {
                    hid[i][2 * q]     = ffma2(vl[i], wl.x, ffma2(vr[i], wr.x, hid[i][2 * q]));
                    hid[i][2 * q + 1] = ffma2(vl[i], wl.y, ffma2(vr[i], wr.y, hid[i][2 * q + 1]));
                }
            }
        }
    } // xp dies here

    // ---- logits + softmax(2): j outer so w2 LDC amortizes over items ----
    u64 lacc[ITEMS];
    {
        const u64 b2v = cW.b2[0];
        #pragma unroll
        for (int i = 0; i < ITEMS; ++i) lacc[i] = b2v;
        const ulonglong2* w2q = (const ulonglong2*)cW.w2;
        #pragma unroll
        for (int j = 0; j < 8; ++j) {
            const ulonglong2 wv = w2q[j];
            #pragma unroll
            for (int i = 0; i < ITEMS; ++i) {
                float h0, h1; upk(hid[i][j], h0, h1);
                h0 = fmaxf(h0, 0.f); h1 = fmaxf(h1, 0.f);
                lacc[i] = ffma2(pk(h0, h0), wv.x, lacc[i]);
                lacc[i] = ffma2(pk(h1, h1), wv.y, lacc[i]);
            }
        }
    }
    float a0v[ITEMS], a1v[ITEMS];
    #pragma unroll
    for (int i = 0; i < ITEMS; ++i) {
        float l0, l1; upk(lacc[i], l0, l1);
        const float e = __expf(l1 - l0);
        a0v[i] = 1.f / (1.f + e);
        a1v[i] = e * a0v[i];
    }

    // ---- gated residual + LayerNorm(16) + stores (natural channel order) ----
    #pragma unroll
    for (int i = 0; i < ITEMS; ++i) {
        const int tglob = tbase + r0 + i;
        const ulonglong2* xrow = (const ulonglong2*)&xs[ROWOFF(r0 + i + 2)];
        const u64 sp0 = pk(1.f + a0v[i], 1.f + a0v[i]);   // L channels scale
        const u64 sp1 = pk(1.f + a1v[i], 1.f + a1v[i]);   // R channels scale
        u64 yp[8];
        u64 sum = pk(0.f, 0.f);
        #pragma unroll
        for (int q = 0; q < 4; ++q) {
            const ulonglong2 v = xrow[q];
            const u64 s = (q < 2) ? sp0 : sp1;
            yp[2 * q]     = fmul2(v.x, s);
            yp[2 * q + 1] = fmul2(v.y, s);
            sum = fadd2(sum, yp[2 * q]);
            sum = fadd2(sum, yp[2 * q + 1]);
        }
        float sE, sO; upk(sum, sE, sO);                    // even/odd channel sums
        const float mu   = (sE + sO) * 0.0625f;
        const u64   nmup = pk(-mu, -mu);
        u64 var2 = pk(0.f, 0.f);
        u64 dp[8];
        #pragma unroll
        for (int c = 0; c < 8; ++c) { dp[c] = fadd2(yp[c], nmup); var2 = ffma2(dp[c], dp[c], var2); }
        float vE, vO; upk(var2, vE, vO);
        const float rs  = rsqrtf((vE + vO) * 0.0625f + 1e-5f);
        const u64   rsp = pk(rs, rs);

        // output pairs in natural order -> direct 16B stores, no unpack shuffle
        ulonglong2* outX = (ulonglong2*)(out + ((size_t)b * T_ + tglob) * 16);
        #pragma unroll
        for (int q = 0; q < 4; ++q) {
            const u64 oA = ffma2(fmul2(dp[2 * q],     rsp), cW.g[2 * q],     cW.bb[2 * q]);
            const u64 oB = ffma2(fmul2(dp[2 * q + 1], rsp), cW.g[2 * q + 1], cW.bb[2 * q + 1]);
            outX[q] = make_ulonglong2(oA, oB);
        }
        float2* outA = (float2*)(out + (size_t)B_ * T_ * 16 + ((size_t)b * T_ + tglob) * 2);
        *outA = make_float2(a0v[i], a1v[i]);
    }
}

extern "C" void kernel_launch(void* const* d_in, const int* in_sizes, int n_in,
                              void* d_out, int out_size)
{
    const float* x      = (const float*)d_in[0];
    const float* conv_w = (const float*)d_in[1];
    const float* conv_b = (const float*)d_in[2];
    const float* w1     = (const float*)d_in[3];
    const float* b1     = (const float*)d_in[4];
    const float* w2     = (const float*)d_in[5];
    const float* b2     = (const float*)d_in[6];
    const float* ln_g   = (const float*)d_in[7];
    const float* ln_b   = (const float*)d_in[8];

    // 1) pack weights into a device staging struct
    prep_kernel<<<1, 128>>>(conv_w, conv_b, w1, b1, w2, b2, ln_g, ln_b);

    // 2) D2D copy staging -> __constant__ (async, graph-capturable memcpy node)
    void* stage_ptr = nullptr;
    cudaGetSymbolAddress(&stage_ptr, dStage);
    cudaMemcpyToSymbolAsync(cW, stage_ptr, sizeof(Wts), 0, cudaMemcpyDeviceToDevice, 0);

    // 3) main kernel
    dim3 grid(T_ / TILE, B_);
    bimanual_kernel<<<grid, THREADS>>>(x, (float*)d_out);
}